// round 1
// baseline (speedup 1.0000x reference)
#include <cuda_runtime.h>
#include <cstdint>

// Problem constants (from reference: N_COLS=16, ADD=3, BATCH=262144)
#define NC        16
#define N_PAIRS   120
#define N_TRIPLES 560
#define N_OUT     696          // 16 + 120 + 560
#define N_OUT4    174          // 696 / 4
#define BLOCK     256
#define ROWS      32           // rows per block
#define ROW_PAD   17           // 16 cols + slot[16] = 1.0f

// ---------------------------------------------------------------------------
// Compile-time subset table. Entry packs (i0 | i1<<8 | i2<<16); index 16 means
// "multiply by 1.0" (a padding slot in the shared x tile), so every output
// column is computed uniformly as xs[i0]*xs[i1]*xs[i2].
// Order matches itertools.combinations lexicographic order exactly.
// ---------------------------------------------------------------------------
struct Tbl { unsigned v[N_OUT]; };

constexpr Tbl make_tbl() {
    Tbl t{};
    int p = 0;
    for (int i = 0; i < NC; i++)
        t.v[p++] = (unsigned)i | (16u << 8) | (16u << 16);
    for (int i = 0; i < NC; i++)
        for (int j = i + 1; j < NC; j++)
            t.v[p++] = (unsigned)i | ((unsigned)j << 8) | (16u << 16);
    for (int i = 0; i < NC; i++)
        for (int j = i + 1; j < NC; j++)
            for (int k = j + 1; k < NC; k++)
                t.v[p++] = (unsigned)i | ((unsigned)j << 8) | ((unsigned)k << 16);
    return t;
}

__constant__ Tbl c_tbl = make_tbl();

// ---------------------------------------------------------------------------
// Kernel: each block processes ROWS=32 rows. x tile + table staged in smem,
// outputs written as coalesced float4 streaming stores.
// ---------------------------------------------------------------------------
__global__ __launch_bounds__(BLOCK)
void algebraic_kernel(const float* __restrict__ x,
                      float* __restrict__ out,
                      int n_rows)
{
    __shared__ float    xs[ROWS][ROW_PAD];
    __shared__ unsigned s_tbl[N_OUT];

    const int tid  = threadIdx.x;
    const int row0 = blockIdx.x * ROWS;

    // Stage the subset table (sequential constant reads -> no serialization).
    #pragma unroll
    for (int i = tid; i < N_OUT; i += BLOCK)
        s_tbl[i] = c_tbl.v[i];

    // Stage 32 rows of x (32*16 floats = 128 float4, coalesced).
    const float4* x4 = (const float4*)(x + (size_t)row0 * NC);
    for (int i = tid; i < ROWS * (NC / 4); i += BLOCK) {
        float4 v = x4[i];
        int r = i >> 2;
        int c = (i & 3) * 4;
        xs[r][c + 0] = v.x;
        xs[r][c + 1] = v.y;
        xs[r][c + 2] = v.z;
        xs[r][c + 3] = v.w;
    }
    if (tid < ROWS) xs[tid][16] = 1.0f;   // identity multiplier slot
    __syncthreads();

    // Flat loop over all float4 outputs of this block's tile.
    float4* out4 = (float4*)(out + (size_t)row0 * N_OUT);
    const uint4* t4 = (const uint4*)s_tbl;

    const int total = ROWS * N_OUT4;      // 5568
    for (int idx = tid; idx < total; idx += BLOCK) {
        int r  = idx / N_OUT4;            // constant divisor -> mul-shift
        int c4 = idx - r * N_OUT4;

        uint4 tt = t4[c4];                // 4 packed entries, one LDS.128
        const float* xr = xs[r];

        float4 o;
        {
            unsigned t = tt.x;
            o.x = xr[t & 31] * xr[(t >> 8) & 31] * xr[(t >> 16) & 31];
        }
        {
            unsigned t = tt.y;
            o.y = xr[t & 31] * xr[(t >> 8) & 31] * xr[(t >> 16) & 31];
        }
        {
            unsigned t = tt.z;
            o.z = xr[t & 31] * xr[(t >> 8) & 31] * xr[(t >> 16) & 31];
        }
        {
            unsigned t = tt.w;
            o.w = xr[t & 31] * xr[(t >> 8) & 31] * xr[(t >> 16) & 31];
        }

        // Streaming store: output has no reuse, don't pollute L2.
        __stcs(&out4[idx], o);
    }
}

extern "C" void kernel_launch(void* const* d_in, const int* in_sizes, int n_in,
                              void* d_out, int out_size)
{
    const float* x = (const float*)d_in[0];
    float* out = (float*)d_out;

    int n_rows = in_sizes[0] / NC;        // 262144
    int n_blocks = (n_rows + ROWS - 1) / ROWS;  // 8192

    algebraic_kernel<<<n_blocks, BLOCK>>>(x, out, n_rows);
}